// round 2
// baseline (speedup 1.0000x reference)
#include <cuda_runtime.h>
#include <math.h>

#define N_NODES 262144
#define E_EDGES 1048576
#define D_IN    384
#define D_BN    128
#define NBOND   4
#define D_Z     640      // (1+4)*128
#define D_OUT   32
#define BN_EPS  1e-5f

// ---------------- scratch (device globals: allowed; no runtime allocation) ---
__device__ __align__(16) float g_h  [(size_t)N_NODES * D_BN];            // 128 MB
__device__ __align__(16) float g_agg[(size_t)N_NODES * NBOND * D_BN];    // 512 MB
__device__ __align__(16) float g_s1[D_IN],  g_b1[D_IN];
__device__ __align__(16) float g_s2[D_Z],   g_b2[D_Z];

__device__ __forceinline__ float elu1(float x) {
    return x > 0.f ? x : (expf(x) - 1.f);
}

// ---------------- precompute BN scale/bias ----------------------------------
__global__ void prep_kernel(const float* __restrict__ g1, const float* __restrict__ b1,
                            const float* __restrict__ m1, const float* __restrict__ v1,
                            const float* __restrict__ g2, const float* __restrict__ b2,
                            const float* __restrict__ m2, const float* __restrict__ v2) {
    int i = threadIdx.x;
    if (i < D_IN) {
        float s = g1[i] * rsqrtf(v1[i] + BN_EPS);
        g_s1[i] = s;
        g_b1[i] = b1[i] - m1[i] * s;
    }
    if (i < D_Z) {
        float s = g2[i] * rsqrtf(v2[i] + BN_EPS);
        g_s2[i] = s;
        g_b2[i] = b2[i] - m2[i] * s;
    }
}

// ---------------- stage 1: h = elu(bn(concat(x1,x2,x3))) @ W1 ----------------
// SGEMM M=262144, N=128, K=384. BM=128, BN=128, BK=16, 256 threads, 8x8/thread.
__global__ __launch_bounds__(256)
void gemm1_kernel(const float* __restrict__ x1, const float* __restrict__ x2,
                  const float* __restrict__ x3, const float* __restrict__ W1) {
    __shared__ float As[16][128];   // [k][m]
    __shared__ float Bs[16][128];   // [k][n]

    const int tid = threadIdx.x;
    const int tx = tid & 15;        // n tile: tx*8
    const int ty = tid >> 4;        // m tile: ty*8
    const int m0 = blockIdx.x * 128;

    float acc[64];
    #pragma unroll
    for (int i = 0; i < 64; i++) acc[i] = 0.f;

    const int a_row  = tid >> 1;            // 0..127
    const int a_half = tid & 1;             // quads {0,1} or {2,3}

    for (int kc = 0; kc < D_IN; kc += 16) {
        // ---- load A tile (with BN + ELU) ----
        const float* xs = (kc < 128) ? x1 : (kc < 256) ? x2 : x3;
        const int colbase = kc & 127;
        #pragma unroll
        for (int j = 0; j < 2; j++) {
            const int quad = a_half * 2 + j;            // 0..3
            float4 v = *reinterpret_cast<const float4*>(
                &xs[(size_t)(m0 + a_row) * 128 + colbase + quad * 4]);
            float4 s = *reinterpret_cast<const float4*>(&g_s1[kc + quad * 4]);
            float4 b = *reinterpret_cast<const float4*>(&g_b1[kc + quad * 4]);
            As[quad * 4 + 0][a_row] = elu1(v.x * s.x + b.x);
            As[quad * 4 + 1][a_row] = elu1(v.y * s.y + b.y);
            As[quad * 4 + 2][a_row] = elu1(v.z * s.z + b.z);
            As[quad * 4 + 3][a_row] = elu1(v.w * s.w + b.w);
        }
        // ---- load B tile ----
        #pragma unroll
        for (int j = 0; j < 2; j++) {
            const int idx = tid * 2 + j;                // 0..511 float4s
            const int k = idx >> 5;                     // 0..15
            const int c4 = idx & 31;                    // 0..31
            float4 w = *reinterpret_cast<const float4*>(
                &W1[(size_t)(kc + k) * 128 + c4 * 4]);
            *reinterpret_cast<float4*>(&Bs[k][c4 * 4]) = w;
        }
        __syncthreads();

        #pragma unroll
        for (int k = 0; k < 16; k++) {
            float a[8], b[8];
            *reinterpret_cast<float4*>(&a[0]) = *reinterpret_cast<const float4*>(&As[k][ty * 8]);
            *reinterpret_cast<float4*>(&a[4]) = *reinterpret_cast<const float4*>(&As[k][ty * 8 + 4]);
            *reinterpret_cast<float4*>(&b[0]) = *reinterpret_cast<const float4*>(&Bs[k][tx * 8]);
            *reinterpret_cast<float4*>(&b[4]) = *reinterpret_cast<const float4*>(&Bs[k][tx * 8 + 4]);
            #pragma unroll
            for (int i = 0; i < 8; i++)
                #pragma unroll
                for (int j = 0; j < 8; j++)
                    acc[i * 8 + j] = fmaf(a[i], b[j], acc[i * 8 + j]);
        }
        __syncthreads();
    }

    #pragma unroll
    for (int i = 0; i < 8; i++) {
        const size_t m = (size_t)(m0 + ty * 8 + i);
        float4 v0 = make_float4(acc[i*8+0], acc[i*8+1], acc[i*8+2], acc[i*8+3]);
        float4 v1 = make_float4(acc[i*8+4], acc[i*8+5], acc[i*8+6], acc[i*8+7]);
        *reinterpret_cast<float4*>(&g_h[m * 128 + tx * 8])     = v0;
        *reinterpret_cast<float4*>(&g_h[m * 128 + tx * 8 + 4]) = v1;
    }
}

// ---------------- stage 2: scatter-add --------------------------------------
// one warp per edge: gather 512B h-row, atomicAdd into agg[(begin*4+bond)*128]
__global__ __launch_bounds__(256)
void scatter_kernel(const int* __restrict__ begin_ids,
                    const int* __restrict__ end_ids,
                    const int* __restrict__ bond_types) {
    const int e = blockIdx.x * 8 + (threadIdx.x >> 5);
    const int lane = threadIdx.x & 31;
    const int bg = begin_ids[e];
    const int src = end_ids[e];
    const int bt = bond_types[e];
    float4 v = *reinterpret_cast<const float4*>(&g_h[(size_t)src * 128 + lane * 4]);
    float* dst = &g_agg[(size_t)(bg * NBOND + bt) * 128 + lane * 4];
    atomicAdd(dst + 0, v.x);
    atomicAdd(dst + 1, v.y);
    atomicAdd(dst + 2, v.z);
    atomicAdd(dst + 3, v.w);
}

// ---------------- stage 3: out = elu(bn([h,agg])) @ W2 -----------------------
// SGEMM M=262144, N=32, K=640. BM=128, BN=32, BK=32, 256 threads, 4x4/thread.
__global__ __launch_bounds__(256)
void gemm2_kernel(const float* __restrict__ W2, float* __restrict__ out) {
    __shared__ float As[32][128];   // [k][m]
    __shared__ float Bs[32][32];    // [k][n]

    const int tid = threadIdx.x;
    const int tx = tid & 7;         // n: tx*4
    const int ty = tid >> 3;        // m: ty*4
    const int m0 = blockIdx.x * 128;

    float acc[16];
    #pragma unroll
    for (int i = 0; i < 16; i++) acc[i] = 0.f;

    for (int kc = 0; kc < D_Z; kc += 32) {
        // ---- load A tile (BN + ELU), source = h (k<128) or agg ----
        #pragma unroll
        for (int j = 0; j < 4; j++) {
            const int idx = j * 256 + tid;      // 0..1023 float4s
            const int row = idx >> 3;           // 0..127
            const int q   = idx & 7;            // 0..7
            const int kk = kc + q * 4;          // global z-col of first elem
            const size_t m = (size_t)(m0 + row);
            float4 v;
            if (kc < 128)
                v = *reinterpret_cast<const float4*>(&g_h[m * 128 + kk]);
            else
                v = *reinterpret_cast<const float4*>(&g_agg[m * 512 + (kk - 128)]);
            float4 s = *reinterpret_cast<const float4*>(&g_s2[kk]);
            float4 b = *reinterpret_cast<const float4*>(&g_b2[kk]);
            As[q * 4 + 0][row] = elu1(v.x * s.x + b.x);
            As[q * 4 + 1][row] = elu1(v.y * s.y + b.y);
            As[q * 4 + 2][row] = elu1(v.z * s.z + b.z);
            As[q * 4 + 3][row] = elu1(v.w * s.w + b.w);
        }
        // ---- load B tile: W2 rows kc..kc+31, all 32 cols ----
        {
            const int k = tid >> 3;             // 0..31
            const int q = tid & 7;              // 0..7
            float4 w = *reinterpret_cast<const float4*>(&W2[(size_t)(kc + k) * 32 + q * 4]);
            *reinterpret_cast<float4*>(&Bs[k][q * 4]) = w;
        }
        __syncthreads();

        #pragma unroll
        for (int k = 0; k < 32; k++) {
            float a[4], b[4];
            *reinterpret_cast<float4*>(a) = *reinterpret_cast<const float4*>(&As[k][ty * 4]);
            *reinterpret_cast<float4*>(b) = *reinterpret_cast<const float4*>(&Bs[k][tx * 4]);
            #pragma unroll
            for (int i = 0; i < 4; i++)
                #pragma unroll
                for (int j = 0; j < 4; j++)
                    acc[i * 4 + j] = fmaf(a[i], b[j], acc[i * 4 + j]);
        }
        __syncthreads();
    }

    #pragma unroll
    for (int i = 0; i < 4; i++) {
        const size_t m = (size_t)(m0 + ty * 4 + i);
        float4 v = make_float4(acc[i*4+0], acc[i*4+1], acc[i*4+2], acc[i*4+3]);
        *reinterpret_cast<float4*>(&out[m * 32 + tx * 4]) = v;
    }
}

// ---------------- launch -----------------------------------------------------
extern "C" void kernel_launch(void* const* d_in, const int* in_sizes, int n_in,
                              void* d_out, int out_size) {
    const float* x1 = (const float*)d_in[0];
    const float* x2 = (const float*)d_in[1];
    const float* x3 = (const float*)d_in[2];
    const int*   begin_ids  = (const int*)d_in[3];
    const int*   end_ids    = (const int*)d_in[4];
    const int*   bond_types = (const int*)d_in[5];
    const float* bn1_gamma = (const float*)d_in[6];
    const float* bn1_beta  = (const float*)d_in[7];
    const float* bn1_mean  = (const float*)d_in[8];
    const float* bn1_var   = (const float*)d_in[9];
    const float* W1        = (const float*)d_in[10];
    const float* bn2_gamma = (const float*)d_in[11];
    const float* bn2_beta  = (const float*)d_in[12];
    const float* bn2_mean  = (const float*)d_in[13];
    const float* bn2_var   = (const float*)d_in[14];
    const float* W2        = (const float*)d_in[15];
    float* out = (float*)d_out;

    prep_kernel<<<1, 640>>>(bn1_gamma, bn1_beta, bn1_mean, bn1_var,
                            bn2_gamma, bn2_beta, bn2_mean, bn2_var);

    // zero agg scratch (graph-capturable async memset on the device symbol)
    void* agg_ptr = nullptr;
    cudaGetSymbolAddress(&agg_ptr, g_agg);
    cudaMemsetAsync(agg_ptr, 0, (size_t)N_NODES * NBOND * D_BN * sizeof(float));

    gemm1_kernel<<<N_NODES / 128, 256>>>(x1, x2, x3, W1);

    scatter_kernel<<<E_EDGES / 8, 256>>>(begin_ids, end_ids, bond_types);

    gemm2_kernel<<<N_NODES / 128, 256>>>(W2, out);
}

// round 5
// speedup vs baseline: 1.5071x; 1.5071x over previous
#include <cuda_runtime.h>
#include <math.h>
#include <stdint.h>

#define N_NODES 262144
#define E_EDGES 1048576
#define D_IN    384
#define D_BN    128
#define NBOND   4
#define D_Z     640      // (1+4)*128
#define D_OUT   32
#define BN_EPS  1e-5f

// ---------------- scratch ----------------------------------------------------
__device__ __align__(16) float g_h  [(size_t)N_NODES * D_BN];            // 128 MB
__device__ __align__(16) float g_agg[(size_t)N_NODES * NBOND * D_BN];    // 512 MB
__device__ __align__(16) float g_s1[D_IN],  g_b1[D_IN];
__device__ __align__(16) float g_s2[D_Z],   g_b2[D_Z];

__device__ __forceinline__ float elu1(float x) {
    return x > 0.f ? x : (expf(x) - 1.f);
}

__device__ __forceinline__ uint32_t f2tf32(float x) {
    uint32_t u;
    asm("cvt.rna.tf32.f32 %0, %1;" : "=r"(u) : "f"(x));
    return u;
}

__device__ __forceinline__ void mma_tf32(float* c, const uint32_t* a, const uint32_t* b) {
    asm volatile(
        "mma.sync.aligned.m16n8k8.row.col.f32.tf32.tf32.f32 "
        "{%0,%1,%2,%3}, {%4,%5,%6,%7}, {%8,%9}, {%0,%1,%2,%3};"
        : "+f"(c[0]), "+f"(c[1]), "+f"(c[2]), "+f"(c[3])
        : "r"(a[0]), "r"(a[1]), "r"(a[2]), "r"(a[3]), "r"(b[0]), "r"(b[1]));
}

// ---------------- precompute BN scale/bias ----------------------------------
__global__ void prep_kernel(const float* __restrict__ g1, const float* __restrict__ b1,
                            const float* __restrict__ m1, const float* __restrict__ v1,
                            const float* __restrict__ g2, const float* __restrict__ b2,
                            const float* __restrict__ m2, const float* __restrict__ v2) {
    int i = threadIdx.x;
    if (i < D_IN) {
        float s = g1[i] * rsqrtf(v1[i] + BN_EPS);
        g_s1[i] = s;
        g_b1[i] = b1[i] - m1[i] * s;
    }
    if (i < D_Z) {
        float s = g2[i] * rsqrtf(v2[i] + BN_EPS);
        g_s2[i] = s;
        g_b2[i] = b2[i] - m2[i] * s;
    }
}

// ============================================================================
// stage 1: h = elu(bn(concat(x1,x2,x3))) @ W1   — TF32 tensor cores
// M=262144, N=128, K=384. BM=128, BN=128, BK=16. 256 thr = 8 warps (4m x 2n).
// Warp tile 32m x 64n: mma grid 2(m16) x 8(n8), k-steps of 8.
// As: m-major [128][20] (pad->conflict-free frag loads, STS.128 staging)
// Bs: k-major [16][136]
// ============================================================================
#define G1_LDA 20
#define G1_LDB 136

__global__ __launch_bounds__(256)
void gemm1_tc(const float* __restrict__ x1, const float* __restrict__ x2,
              const float* __restrict__ x3, const float* __restrict__ W1) {
    __shared__ uint32_t As[128 * G1_LDA];   // 10.2 KB
    __shared__ uint32_t Bs[16 * G1_LDB];    // 8.7 KB

    const int tid  = threadIdx.x;
    const int lane = tid & 31;
    const int w    = tid >> 5;
    const int wm   = w >> 1;           // 0..3 -> m offset wm*32
    const int wn   = w & 1;            // 0..1 -> n offset wn*64
    const int grp  = lane >> 2;        // 0..7
    const int qid  = lane & 3;         // 0..3
    const int m0   = blockIdx.x * 128;

    float acc[2][8][4];
    #pragma unroll
    for (int i = 0; i < 2; i++)
        #pragma unroll
        for (int j = 0; j < 8; j++)
            #pragma unroll
            for (int r = 0; r < 4; r++) acc[i][j][r] = 0.f;

    const int a_row  = tid >> 1;       // 0..127
    const int a_half = tid & 1;

    for (int kc = 0; kc < D_IN; kc += 16) {
        const float* xs = (kc < 128) ? x1 : (kc < 256) ? x2 : x3;
        const int colbase = kc & 127;

        // ---- stage A tile (BN + ELU + tf32), STS.128 ----
        #pragma unroll
        for (int j = 0; j < 2; j++) {
            const int quad = a_half * 2 + j;           // 0..3 -> k cols quad*4..+3
            float4 v = *reinterpret_cast<const float4*>(
                &xs[(size_t)(m0 + a_row) * 128 + colbase + quad * 4]);
            float4 s = *reinterpret_cast<const float4*>(&g_s1[kc + quad * 4]);
            float4 b = *reinterpret_cast<const float4*>(&g_b1[kc + quad * 4]);
            uint4 t;
            t.x = f2tf32(elu1(v.x * s.x + b.x));
            t.y = f2tf32(elu1(v.y * s.y + b.y));
            t.z = f2tf32(elu1(v.z * s.z + b.z));
            t.w = f2tf32(elu1(v.w * s.w + b.w));
            *reinterpret_cast<uint4*>(&As[a_row * G1_LDA + quad * 4]) = t;
        }
        // ---- stage B tile: W1 rows kc..kc+15, 128 cols ----
        #pragma unroll
        for (int j = 0; j < 2; j++) {
            const int idx = j * 256 + tid;             // 0..511 float4s
            const int k  = idx >> 5;                   // 0..15
            const int c4 = idx & 31;                   // 0..31
            float4 wv = *reinterpret_cast<const float4*>(
                &W1[(size_t)(kc + k) * 128 + c4 * 4]);
            uint4 t;
            t.x = f2tf32(wv.x); t.y = f2tf32(wv.y);
            t.z = f2tf32(wv.z); t.w = f2tf32(wv.w);
            *reinterpret_cast<uint4*>(&Bs[k * G1_LDB + c4 * 4]) = t;
        }
        __syncthreads();

        #pragma unroll
        for (int kk = 0; kk < 16; kk += 8) {
            uint32_t af[2][4];
            #pragma unroll
            for (int mi = 0; mi < 2; mi++) {
                const int r0 = wm * 32 + mi * 16 + grp;
                af[mi][0] = As[r0 * G1_LDA + kk + qid];
                af[mi][1] = As[(r0 + 8) * G1_LDA + kk + qid];
                af[mi][2] = As[r0 * G1_LDA + kk + qid + 4];
                af[mi][3] = As[(r0 + 8) * G1_LDA + kk + qid + 4];
            }
            uint32_t bf[8][2];
            #pragma unroll
            for (int ni = 0; ni < 8; ni++) {
                const int col = wn * 64 + ni * 8 + grp;
                bf[ni][0] = Bs[(kk + qid) * G1_LDB + col];
                bf[ni][1] = Bs[(kk + qid + 4) * G1_LDB + col];
            }
            #pragma unroll
            for (int mi = 0; mi < 2; mi++)
                #pragma unroll
                for (int ni = 0; ni < 8; ni++)
                    mma_tf32(acc[mi][ni], af[mi], bf[ni]);
        }
        __syncthreads();
    }

    // ---- epilogue: write h ----
    #pragma unroll
    for (int mi = 0; mi < 2; mi++) {
        const int row = m0 + wm * 32 + mi * 16 + grp;
        #pragma unroll
        for (int ni = 0; ni < 8; ni++) {
            const int col = wn * 64 + ni * 8 + 2 * qid;
            *reinterpret_cast<float2*>(&g_h[(size_t)row * 128 + col]) =
                make_float2(acc[mi][ni][0], acc[mi][ni][1]);
            *reinterpret_cast<float2*>(&g_h[(size_t)(row + 8) * 128 + col]) =
                make_float2(acc[mi][ni][2], acc[mi][ni][3]);
        }
    }
}

// ---------------- stage 2: scatter-add --------------------------------------
__global__ __launch_bounds__(256)
void scatter_kernel(const int* __restrict__ begin_ids,
                    const int* __restrict__ end_ids,
                    const int* __restrict__ bond_types) {
    const int e = blockIdx.x * 8 + (threadIdx.x >> 5);
    const int lane = threadIdx.x & 31;
    const int bg = begin_ids[e];
    const int src = end_ids[e];
    const int bt = bond_types[e];
    float4 v = *reinterpret_cast<const float4*>(&g_h[(size_t)src * 128 + lane * 4]);
    float* dst = &g_agg[(size_t)(bg * NBOND + bt) * 128 + lane * 4];
    atomicAdd(dst + 0, v.x);
    atomicAdd(dst + 1, v.y);
    atomicAdd(dst + 2, v.z);
    atomicAdd(dst + 3, v.w);
}

// ============================================================================
// stage 3: out = elu(bn([h,agg])) @ W2 — TF32 tensor cores
// M=262144, N=32, K=640. BM=128, BN=32, BK=32. 256 thr = 8 warps (8m x 1n).
// Warp tile 16m x 32n: mma grid 1(m16) x 4(n8), k-steps of 8.
// As: m-major [128][36]; Bs: k-major [32][40]
// ============================================================================
#define G2_LDA 36
#define G2_LDB 40

__global__ __launch_bounds__(256)
void gemm2_tc(const float* __restrict__ W2, float* __restrict__ out) {
    __shared__ uint32_t As[128 * G2_LDA];   // 18.4 KB
    __shared__ uint32_t Bs[32 * G2_LDB];    // 5.1 KB

    const int tid  = threadIdx.x;
    const int lane = tid & 31;
    const int w    = tid >> 5;         // 0..7 -> m offset w*16
    const int grp  = lane >> 2;        // 0..7
    const int qid  = lane & 3;         // 0..3
    const int m0   = blockIdx.x * 128;

    float acc[4][4];
    #pragma unroll
    for (int i = 0; i < 4; i++)
        #pragma unroll
        for (int r = 0; r < 4; r++) acc[i][r] = 0.f;

    for (int kc = 0; kc < D_Z; kc += 32) {
        // ---- stage A tile: 128 rows x 32 k, BN+ELU+tf32, STS.128 ----
        #pragma unroll
        for (int j = 0; j < 4; j++) {
            const int idx = j * 256 + tid;     // 0..1023 float4s
            const int row = idx >> 3;          // 0..127
            const int q   = idx & 7;           // 0..7 -> k cols q*4..+3
            const int kk  = kc + q * 4;
            const size_t m = (size_t)(m0 + row);
            float4 v;
            if (kc < 128)
                v = *reinterpret_cast<const float4*>(&g_h[m * 128 + kk]);
            else
                v = *reinterpret_cast<const float4*>(&g_agg[m * 512 + (kk - 128)]);
            float4 s = *reinterpret_cast<const float4*>(&g_s2[kk]);
            float4 b = *reinterpret_cast<const float4*>(&g_b2[kk]);
            uint4 t;
            t.x = f2tf32(elu1(v.x * s.x + b.x));
            t.y = f2tf32(elu1(v.y * s.y + b.y));
            t.z = f2tf32(elu1(v.z * s.z + b.z));
            t.w = f2tf32(elu1(v.w * s.w + b.w));
            *reinterpret_cast<uint4*>(&As[row * G2_LDA + q * 4]) = t;
        }
        // ---- stage B tile: W2 rows kc..kc+31, 32 cols = 256 float4 ----
        {
            const int k  = tid >> 3;           // 0..31
            const int c4 = tid & 7;            // 0..7
            float4 wv = *reinterpret_cast<const float4*>(
                &W2[(size_t)(kc + k) * 32 + c4 * 4]);
            uint4 t;
            t.x = f2tf32(wv.x); t.y = f2tf32(wv.y);
            t.z = f2tf32(wv.z); t.w = f2tf32(wv.w);
            *reinterpret_cast<uint4*>(&Bs[k * G2_LDB + c4 * 4]) = t;
        }
        __syncthreads();

        #pragma unroll
        for (int kk = 0; kk < 32; kk += 8) {
            uint32_t af[4];
            const int r0 = w * 16 + grp;
            af[0] = As[r0 * G2_LDA + kk + qid];
            af[1] = As[(r0 + 8) * G2_LDA + kk + qid];
            af[2] = As[r0 * G2_LDA + kk + qid + 4];
            af[3] = As[(r0 + 8) * G2_LDA + kk + qid + 4];
            uint32_t bf[4][2];
            #pragma unroll
            for (int ni = 0; ni < 4; ni++) {
                const int col = ni * 8 + grp;
                bf[ni][0] = Bs[(kk + qid) * G2_LDB + col];
                bf[ni][1] = Bs[(kk + qid + 4) * G2_LDB + col];
            }
            #pragma unroll
            for (int ni = 0; ni < 4; ni++)
                mma_tf32(acc[ni], af, bf[ni]);
        }
        __syncthreads();
    }

    // ---- epilogue ----
    {
        const int row = m0 + w * 16 + grp;
        #pragma unroll
        for (int ni = 0; ni < 4; ni++) {
            const int col = ni * 8 + 2 * qid;
            *reinterpret_cast<float2*>(&out[(size_t)row * 32 + col]) =
                make_float2(acc[ni][0], acc[ni][1]);
            *reinterpret_cast<float2*>(&out[(size_t)(row + 8) * 32 + col]) =
                make_float2(acc[ni][2], acc[ni][3]);
        }
    }
}

// ---------------- launch -----------------------------------------------------
extern "C" void kernel_launch(void* const* d_in, const int* in_sizes, int n_in,
                              void* d_out, int out_size) {
    const float* x1 = (const float*)d_in[0];
    const float* x2 = (const float*)d_in[1];
    const float* x3 = (const float*)d_in[2];
    const int*   begin_ids  = (const int*)d_in[3];
    const int*   end_ids    = (const int*)d_in[4];
    const int*   bond_types = (const int*)d_in[5];
    const float* bn1_gamma = (const float*)d_in[6];
    const float* bn1_beta  = (const float*)d_in[7];
    const float* bn1_mean  = (const float*)d_in[8];
    const float* bn1_var   = (const float*)d_in[9];
    const float* W1        = (const float*)d_in[10];
    const float* bn2_gamma = (const float*)d_in[11];
    const float* bn2_beta  = (const float*)d_in[12];
    const float* bn2_mean  = (const float*)d_in[13];
    const float* bn2_var   = (const float*)d_in[14];
    const float* W2        = (const float*)d_in[15];
    float* out = (float*)d_out;

    prep_kernel<<<1, 640>>>(bn1_gamma, bn1_beta, bn1_mean, bn1_var,
                            bn2_gamma, bn2_beta, bn2_mean, bn2_var);

    void* agg_ptr = nullptr;
    cudaGetSymbolAddress(&agg_ptr, g_agg);
    cudaMemsetAsync(agg_ptr, 0, (size_t)N_NODES * NBOND * D_BN * sizeof(float));

    gemm1_tc<<<N_NODES / 128, 256>>>(x1, x2, x3, W1);

    scatter_kernel<<<E_EDGES / 8, 256>>>(begin_ids, end_ids, bond_types);

    gemm2_tc<<<N_NODES / 128, 256>>>(W2, out);
}